// round 16
// baseline (speedup 1.0000x reference)
#include <cuda_runtime.h>
#include <cuda_bf16.h>
#include <cuda_fp16.h>
#include <math.h>

#define N_NODES 50000
#define N_EDGES 800000
#define HDIM    128
#define FIN     64
#define NGRAPH  64
#define NOUT    16
#define SCAN_NB 49
#define POOL_SPLIT 8
#define GEMM_BLOCKS 391   // ceil(50000/128)
#define WPREP_N (3 * 8 * 128 * 4)
#define FEAT_N (N_NODES * 64)

// -------- device scratch --------
__device__ __align__(16) uint2 d_hS[N_NODES * 64];     // bf16 hi/lo split (gemm input)
__device__ __align__(16) unsigned d_hH[N_NODES * 64];  // fp16x2 gemm output (gather source)
__device__ __align__(16) float d_hA[N_NODES * HDIM];   // fp32 final-layer agg (pool input)
__device__ __align__(16) float d_wabs[N_EDGES];
__device__ __align__(16) float d_deg[N_NODES];
__device__ __align__(16) int   d_cnt[N_NODES];
__device__ __align__(16) int   d_off[N_NODES + 1];
__device__ __align__(16) int   d_cur[N_NODES];
__device__ __align__(16) int2  d_edge[N_EDGES];
__device__ __align__(16) int   d_row[N_EDGES];
__device__ __align__(16) int   d_col[N_EDGES];
__device__ __align__(16) int   d_bsum[SCAN_NB + 1];
__device__ __align__(16) int   d_gstart[NGRAPH + 1];
__device__ __align__(16) float d_pool[NGRAPH * HDIM];
__device__ __align__(16) uint4 d_Wt[3][8][128][4];
__device__ int d_is64g;

// -------- helpers --------
__device__ __forceinline__ bool is_nan_bits(float v) {
    unsigned u = __float_as_uint(v);
    return (u & 0x7fffffffu) > 0x7f800000u;
}
__device__ __forceinline__ float nan_to_zero(float v) {
    return is_nan_bits(v) ? 0.0f : v;
}
__device__ __forceinline__ void split2(float2 v, unsigned& hi, unsigned& lo) {
    unsigned h;
    asm("cvt.rn.bf16x2.f32 %0, %1, %2;" : "=r"(h) : "f"(v.y), "f"(v.x));
    float h0 = __uint_as_float(h << 16);
    float h1 = __uint_as_float(h & 0xffff0000u);
    unsigned l;
    asm("cvt.rn.bf16x2.f32 %0, %1, %2;" : "=r"(l) : "f"(v.y - h1), "f"(v.x - h0));
    hi = h;
    lo = l;
}
__device__ __forceinline__ unsigned pack_f16x2(float lo, float hi) {
    unsigned u;
    asm("cvt.rn.f16x2.f32 %0, %1, %2;" : "=r"(u) : "f"(hi), "f"(lo));
    return u;
}
__device__ __forceinline__ float2 unpack_f16x2(unsigned u) {
    __half2 h = *reinterpret_cast<const __half2*>(&u);
    return __half22float2(h);
}
__device__ __forceinline__ void mma_bf16(float* c, unsigned a0, unsigned a1,
                                         unsigned a2, unsigned a3,
                                         unsigned b0, unsigned b1) {
    asm volatile(
        "mma.sync.aligned.m16n8k16.row.col.f32.bf16.bf16.f32 "
        "{%0,%1,%2,%3}, {%4,%5,%6,%7}, {%8,%9}, {%0,%1,%2,%3};"
        : "+f"(c[0]), "+f"(c[1]), "+f"(c[2]), "+f"(c[3])
        : "r"(a0), "r"(a1), "r"(a2), "r"(a3), "r"(b0), "r"(b1));
}

// -------- 1. init counters + pool + dtype detect --------
__global__ void init_kernel(const int* __restrict__ eraw) {
    int t = blockIdx.x * blockDim.x + threadIdx.x;
    if (t == 0) {
        int any = 0;
#pragma unroll
        for (int k = 0; k < 64; k++) any |= eraw[2 * k + 1];
        d_is64g = (any == 0) ? 1 : 0;
    }
    if (t < N_NODES) {
        d_deg[t] = 0.0f;
        d_cnt[t] = 0;
        d_cur[t] = 0;
    }
    if (t < NGRAPH * HDIM) d_pool[t] = 0.0f;
}

// -------- 2. side stream: edge convert + |w| + degree atomics + bounds --------
__global__ void cvt_edge_kernel(const int* __restrict__ eraw,
                                const int* __restrict__ braw,
                                const float* __restrict__ attr) {
    int t = blockIdx.x * blockDim.x + threadIdx.x;
    int is64 = d_is64g;
    if (t < N_EDGES) {
        int r, c;
        if (is64) {
            r = eraw[2 * t];
            c = eraw[2 * (N_EDGES + t)];
        } else {
            r = eraw[t];
            c = eraw[N_EDGES + t];
        }
        d_row[t] = r;
        d_col[t] = c;
        float w = fabsf(nan_to_zero(attr[t]));
        d_wabs[t] = w;
        atomicAdd(&d_deg[c], w);
        atomicAdd(&d_cnt[c], 1);
    }
    if (t < N_NODES) {
        int b    = is64 ? braw[2 * t] : braw[t];
        int prev = (t == 0) ? -1 : (is64 ? braw[2 * (t - 1)] : braw[t - 1]);
        if (prev != b) {
            for (int g = prev + 1; g <= b; g++) d_gstart[g] = t;
        }
        if (t == N_NODES - 1) {
            for (int g = b + 1; g <= NGRAPH; g++) d_gstart[g] = N_NODES;
        }
    }
}

// -------- 3. main stream: feature init (split bf16) + W prep --------
__global__ void feat_init_kernel(const float* __restrict__ x,
                                 const float* __restrict__ W0,
                                 const float* __restrict__ W1,
                                 const float* __restrict__ W2) {
    int t = blockIdx.x * blockDim.x + threadIdx.x;
    if (t < FEAT_N) {
        int i = t >> 6;
        int kq = t & 63;
        int f0 = kq * 2;
        float v0, v1;
        if (f0 < FIN) {
            v0 = nan_to_zero(x[i * FIN + f0]);
            v1 = nan_to_zero(x[i * FIN + f0 + 1]);
        } else {
            v0 = is_nan_bits(x[i * FIN + f0 - FIN]) ? 1.0f : 0.0f;
            v1 = is_nan_bits(x[i * FIN + f0 + 1 - FIN]) ? 1.0f : 0.0f;
        }
        unsigned hi, lo;
        split2(make_float2(v0, v1), hi, lo);
        d_hS[t] = make_uint2(hi, lo);
    } else if (t < FEAT_N + WPREP_N) {
        int u = t - FEAT_N;
        int layer = u >> 12;
        int rem = u & 4095;
        int ks = rem >> 9;
        int n = (rem >> 2) & 127;
        int q = rem & 3;
        const float* W = (layer == 0) ? W0 : (layer == 1) ? W1 : W2;
        int kb = ks * 16 + 2 * q;
        float2 vA = make_float2(W[kb * HDIM + n],       W[(kb + 1) * HDIM + n]);
        float2 vB = make_float2(W[(kb + 8) * HDIM + n], W[(kb + 9) * HDIM + n]);
        unsigned hA, lA, hB, lB;
        split2(vA, hA, lA);
        split2(vB, hB, lB);
        uint4 pk;
        pk.x = hA;
        pk.y = hB;
        pk.z = lA;
        pk.w = lB;
        d_Wt[layer][ks][n][q] = pk;
    }
}

// -------- 4. GEMM: 32x64 warp tile, pre-split A, fp16 epilogue --------
__global__ void __launch_bounds__(256, 2) gemm_mma_kernel(int layer) {
    const int tid = threadIdx.x;
    const int wid = tid >> 5;
    const int lane = tid & 31;
    const int wrow = wid >> 1;
    const int wcol = wid & 1;
    const int row_base = blockIdx.x * 128 + wrow * 32;
    const int col_base = wcol * 64;
    const int r = lane >> 2;            // 0..7
    const int lq = lane & 3;            // 0..3

    float acc[2][8][4];
#pragma unroll
    for (int mt = 0; mt < 2; mt++)
#pragma unroll
        for (int nt = 0; nt < 8; nt++)
#pragma unroll
            for (int j = 0; j < 4; j++) acc[mt][nt][j] = 0.0f;

#pragma unroll
    for (int ks = 0; ks < 8; ks++) {
        const int kq = ks * 8 + lq;
        unsigned ahi[2][4], alo[2][4];
#pragma unroll
        for (int mt = 0; mt < 2; mt++) {
            int r0 = row_base + mt * 16 + r;
            int r1 = r0 + 8;
            uint2 z = make_uint2(0u, 0u);
            uint2 p0 = (r0 < N_NODES) ? d_hS[r0 * 64 + kq]     : z;
            uint2 p1 = (r1 < N_NODES) ? d_hS[r1 * 64 + kq]     : z;
            uint2 p2 = (r0 < N_NODES) ? d_hS[r0 * 64 + kq + 4] : z;
            uint2 p3 = (r1 < N_NODES) ? d_hS[r1 * 64 + kq + 4] : z;
            ahi[mt][0] = p0.x; alo[mt][0] = p0.y;
            ahi[mt][1] = p1.x; alo[mt][1] = p1.y;
            ahi[mt][2] = p2.x; alo[mt][2] = p2.y;
            ahi[mt][3] = p3.x; alo[mt][3] = p3.y;
        }
        const uint4* wbase = &d_Wt[layer][ks][col_base][0];
#pragma unroll
        for (int nt = 0; nt < 8; nt++) {
            uint4 w = wbase[nt * 32 + lane];
#pragma unroll
            for (int mt = 0; mt < 2; mt++) {
                mma_bf16(acc[mt][nt], ahi[mt][0], ahi[mt][1], ahi[mt][2], ahi[mt][3], w.x, w.y);
                mma_bf16(acc[mt][nt], ahi[mt][0], ahi[mt][1], ahi[mt][2], ahi[mt][3], w.z, w.w);
                mma_bf16(acc[mt][nt], alo[mt][0], alo[mt][1], alo[mt][2], alo[mt][3], w.x, w.y);
            }
        }
    }
    // epilogue: pack to fp16x2
#pragma unroll
    for (int mt = 0; mt < 2; mt++) {
        int r0 = row_base + mt * 16 + r;
        int r1 = r0 + 8;
#pragma unroll
        for (int nt = 0; nt < 8; nt++) {
            int cc = col_base + nt * 8 + (lq * 2);
            if (r0 < N_NODES)
                d_hH[r0 * 64 + (cc >> 1)] = pack_f16x2(acc[mt][nt][0], acc[mt][nt][1]);
            if (r1 < N_NODES)
                d_hH[r1 * 64 + (cc >> 1)] = pack_f16x2(acc[mt][nt][2], acc[mt][nt][3]);
        }
    }
}

// -------- scan / scatter --------
__global__ void scan1_kernel() {
    __shared__ int sh[1024];
    int t = threadIdx.x;
    int b = blockIdx.x;
    int i = b * 1024 + t;
    int v = (i < N_NODES) ? d_cnt[i] : 0;
    sh[t] = v;
    __syncthreads();
#pragma unroll
    for (int ofs = 1; ofs < 1024; ofs <<= 1) {
        int u = (t >= ofs) ? sh[t - ofs] : 0;
        __syncthreads();
        sh[t] += u;
        __syncthreads();
    }
    if (i < N_NODES) d_off[i] = sh[t] - v;
    if (t == 1023) d_bsum[b] = sh[1023];
}
__global__ void scan2_kernel() {
    __shared__ int pre[SCAN_NB + 1];
    int t = threadIdx.x;
    int b = blockIdx.x;
    if (t == 0) {
        int run = 0;
#pragma unroll
        for (int j = 0; j < SCAN_NB; j++) { pre[j] = run; run += d_bsum[j]; }
        pre[SCAN_NB] = run;
    }
    __syncthreads();
    int i = b * 1024 + t;
    if (i < N_NODES) d_off[i] += pre[b];
    if (b == 0 && t == 0) d_off[N_NODES] = pre[SCAN_NB];
}
__global__ void scatter_kernel() {
    int e = blockIdx.x * blockDim.x + threadIdx.x;
    if (e >= N_EDGES) return;
    int r = d_row[e];
    int c = d_col[e];
    float w = d_wabs[e];
    int p = d_off[c] + atomicAdd(&d_cur[c], 1);
    float nrm = rsqrtf(d_deg[r] + 1.0f) * w * rsqrtf(d_deg[c] + 1.0f);
    int2 pk;
    pk.x = r;
    pk.y = __float_as_int(nrm);
    d_edge[p] = pk;
}

// -------- aggregation: fp16 gather (8-unrolled) + self-loop + bias [+ BN/ReLU] --------
template <bool DO_BN>
__global__ void __launch_bounds__(512) agg_kernel(const float* __restrict__ bias,
                           const float* __restrict__ gamma,
                           const float* __restrict__ beta,
                           const float* __restrict__ mean,
                           const float* __restrict__ var) {
    int warp = (blockIdx.x * blockDim.x + threadIdx.x) >> 5;
    int lane = threadIdx.x & 31;
    if (warp >= N_NODES) return;
    const int i = warp;
    const int fs = lane * 4;
    const uint2* __restrict__ hrows = reinterpret_cast<const uint2*>(d_hH);
    int s = d_off[i];
    int e = d_off[i + 1];

    float ax = 0.f, ay = 0.f, az = 0.f, aw = 0.f;
    int p = s;
    // 8-wide unroll: 8 independent gathers in flight
    for (; p + 7 < e; p += 8) {
        int2 em[8];
        uint2 q[8];
#pragma unroll
        for (int j = 0; j < 8; j++) em[j] = d_edge[p + j];
#pragma unroll
        for (int j = 0; j < 8; j++) q[j] = hrows[em[j].x * 32 + lane];
#pragma unroll
        for (int j = 0; j < 8; j++) {
            float n = __int_as_float(em[j].y);
            float2 a = unpack_f16x2(q[j].x);
            float2 b = unpack_f16x2(q[j].y);
            ax += n * a.x;
            ay += n * a.y;
            az += n * b.x;
            aw += n * b.y;
        }
    }
    for (; p < e; p++) {
        int2 e0 = d_edge[p];
        float n0 = __int_as_float(e0.y);
        uint2 q0 = hrows[e0.x * 32 + lane];
        float2 a0 = unpack_f16x2(q0.x), b0 = unpack_f16x2(q0.y);
        ax += n0 * a0.x;
        ay += n0 * a0.y;
        az += n0 * b0.x;
        aw += n0 * b0.y;
    }
    float sl = 1.0f / (d_deg[i] + 1.0f);
    {
        uint2 qv = hrows[i * 32 + lane];
        float2 av = unpack_f16x2(qv.x), bv = unpack_f16x2(qv.y);
        ax += sl * av.x;
        ay += sl * av.y;
        az += sl * bv.x;
        aw += sl * bv.y;
    }
    ax += bias[fs + 0];
    ay += bias[fs + 1];
    az += bias[fs + 2];
    aw += bias[fs + 3];

    if (DO_BN) {
        float g0 = gamma[fs + 0], g1 = gamma[fs + 1], g2 = gamma[fs + 2], g3 = gamma[fs + 3];
        float e0 = beta[fs + 0],  e1 = beta[fs + 1],  e2 = beta[fs + 2],  e3 = beta[fs + 3];
        float m0 = mean[fs + 0],  m1 = mean[fs + 1],  m2 = mean[fs + 2],  m3 = mean[fs + 3];
        float v0 = var[fs + 0],   v1 = var[fs + 1],   v2 = var[fs + 2],   v3 = var[fs + 3];
        ax = fmaxf(0.0f, (ax - m0) * (g0 * rsqrtf(v0 + 1e-5f)) + e0);
        ay = fmaxf(0.0f, (ay - m1) * (g1 * rsqrtf(v1 + 1e-5f)) + e1);
        az = fmaxf(0.0f, (az - m2) * (g2 * rsqrtf(v2 + 1e-5f)) + e2);
        aw = fmaxf(0.0f, (aw - m3) * (g3 * rsqrtf(v3 + 1e-5f)) + e3);
        unsigned h0u, l0u, h1u, l1u;
        split2(make_float2(ax, ay), h0u, l0u);
        split2(make_float2(az, aw), h1u, l1u);
        uint4 pk;
        pk.x = h0u;
        pk.y = l0u;
        pk.z = h1u;
        pk.w = l1u;
        *reinterpret_cast<uint4*>(&d_hS[i * 64 + lane * 2]) = pk;
    } else {
        float4 out = make_float4(ax, ay, az, aw);
        *reinterpret_cast<float4*>(&d_hA[i * HDIM + fs]) = out;
    }
}

// -------- pool + MLP --------
__global__ void pool_kernel() {
    int g = blockIdx.x;
    int part = blockIdx.y;
    int f = threadIdx.x;
    int s = d_gstart[g];
    int e = d_gstart[g + 1];
    int len = e - s;
    int chunk = (len + POOL_SPLIT - 1) / POOL_SPLIT;
    int ps = s + part * chunk;
    int pe = min(ps + chunk, e);
    float a = 0.f;
    for (int n = ps; n < pe; n++) a += d_hA[n * HDIM + f];
    float cnt = (float)len;
    if (ps < pe) atomicAdd(&d_pool[g * HDIM + f], a / fmaxf(cnt, 1.0f));
}
__global__ void mlp_kernel(const float* __restrict__ mW1,
                           const float* __restrict__ mb1,
                           const float* __restrict__ mW2,
                           const float* __restrict__ mb2,
                           float* __restrict__ out) {
    __shared__ __align__(16) float gi[HDIM];
    __shared__ __align__(16) float hid[HDIM];
    int g = blockIdx.x;
    int t = threadIdx.x;
    gi[t] = d_pool[g * HDIM + t];
    __syncthreads();
    float acc = mb1[t];
#pragma unroll 4
    for (int k = 0; k < HDIM; k++) acc += gi[k] * mW1[k * HDIM + t];
    hid[t] = 0.5f * acc * (1.0f + erff(acc * 0.70710678118654752f));
    __syncthreads();
    if (t < NOUT) {
        float o = mb2[t];
#pragma unroll 4
        for (int k = 0; k < HDIM; k++) o += hid[k] * mW2[k * NOUT + t];
        out[g * NOUT + t] = o;
    }
}

// -------- launch --------
extern "C" void kernel_launch(void* const* d_in, const int* in_sizes, int n_in,
                              void* d_out, int out_size) {
    const float* x     = (const float*)d_in[0];
    const int*   eraw  = (const int*)d_in[1];
    const float* attr  = (const float*)d_in[2];
    const int*   braw  = (const int*)d_in[3];
    const float* W0 = (const float*)d_in[4];
    const float* b0 = (const float*)d_in[5];
    const float* W1 = (const float*)d_in[6];
    const float* b1 = (const float*)d_in[7];
    const float* W2 = (const float*)d_in[8];
    const float* b2 = (const float*)d_in[9];
    const float* bn_gamma = (const float*)d_in[10];
    const float* bn_beta  = (const float*)d_in[11];
    const float* bn_mean  = (const float*)d_in[12];
    const float* bn_var   = (const float*)d_in[13];
    const float* mW1 = (const float*)d_in[14];
    const float* mb1 = (const float*)d_in[15];
    const float* mW2 = (const float*)d_in[16];
    const float* mb2 = (const float*)d_in[17];
    float* out = (float*)d_out;

    static cudaStream_t s2 = nullptr;
    static cudaEvent_t evA = nullptr, evB = nullptr;
    if (s2 == nullptr) {
        cudaStreamCreateWithFlags(&s2, cudaStreamNonBlocking);
        cudaEventCreateWithFlags(&evA, cudaEventDisableTiming);
        cudaEventCreateWithFlags(&evB, cudaEventDisableTiming);
    }

    const int TB = 256;
    const int agg_blocks = (N_NODES + 15) / 16;   // 16 warps per 512-thread block

    // main stream: init -> feat_init(+wprep) -> gemm0
    init_kernel<<<(N_NODES + TB - 1) / TB, TB>>>(eraw);
    cudaEventRecord(evA, 0);
    feat_init_kernel<<<(FEAT_N + WPREP_N + TB - 1) / TB, TB>>>(x, W0, W1, W2);
    gemm_mma_kernel<<<GEMM_BLOCKS, 256>>>(0);

    // side stream (forked after init): CSR build
    cudaStreamWaitEvent(s2, evA, 0);
    cvt_edge_kernel<<<(N_EDGES + TB - 1) / TB, TB, 0, s2>>>(eraw, braw, attr);
    scan1_kernel<<<SCAN_NB, 1024, 0, s2>>>();
    scan2_kernel<<<SCAN_NB, 1024, 0, s2>>>();
    scatter_kernel<<<(N_EDGES + TB - 1) / TB, TB, 0, s2>>>();
    cudaEventRecord(evB, s2);

    // join
    cudaStreamWaitEvent(0, evB, 0);
    agg_kernel<true><<<agg_blocks, 512>>>(b0, bn_gamma, bn_beta, bn_mean, bn_var);
    gemm_mma_kernel<<<GEMM_BLOCKS, 256>>>(1);
    agg_kernel<true><<<agg_blocks, 512>>>(b1, bn_gamma, bn_beta, bn_mean, bn_var);
    gemm_mma_kernel<<<GEMM_BLOCKS, 256>>>(2);
    agg_kernel<false><<<agg_blocks, 512>>>(b2, bn_gamma, bn_beta, bn_mean, bn_var);

    dim3 pool_grid(NGRAPH, POOL_SPLIT);
    pool_kernel<<<pool_grid, HDIM>>>();
    mlp_kernel<<<NGRAPH, HDIM>>>(mW1, mb1, mW2, mb2, out);
}

// round 17
// speedup vs baseline: 1.0203x; 1.0203x over previous
#include <cuda_runtime.h>
#include <cuda_bf16.h>
#include <cuda_fp16.h>
#include <math.h>

#define N_NODES 50000
#define N_EDGES 800000
#define HDIM    128
#define FIN     64
#define NGRAPH  64
#define NOUT    16
#define SCAN_NB 49
#define POOL_SPLIT 8
#define GEMM_BLOCKS 391   // ceil(50000/128)
#define WPREP_N (3 * 8 * 128 * 4)
#define FEAT_N (N_NODES * 64)

// -------- device scratch --------
__device__ __align__(16) uint2 d_hS[N_NODES * 64];     // bf16 hi/lo split (gemm input)
__device__ __align__(16) unsigned d_hH[N_NODES * 64];  // fp16x2 gemm output (gather source)
__device__ __align__(16) float d_hA[N_NODES * HDIM];   // fp32 final-layer agg (pool input)
__device__ __align__(16) float d_wabs[N_EDGES];
__device__ __align__(16) float d_deg[N_NODES];
__device__ __align__(16) int   d_cnt[N_NODES];
__device__ __align__(16) int   d_off[N_NODES + 1];
__device__ __align__(16) int   d_cur[N_NODES];
__device__ __align__(16) int2  d_edge[N_EDGES];
__device__ __align__(16) int   d_row[N_EDGES];
__device__ __align__(16) int   d_col[N_EDGES];
__device__ __align__(16) int   d_bsum[SCAN_NB + 1];
__device__ __align__(16) int   d_gstart[NGRAPH + 1];
__device__ __align__(16) float d_pool[NGRAPH * HDIM];
__device__ __align__(16) uint4 d_Wt[3][8][128][4];
__device__ int d_is64g;

// -------- helpers --------
__device__ __forceinline__ bool is_nan_bits(float v) {
    unsigned u = __float_as_uint(v);
    return (u & 0x7fffffffu) > 0x7f800000u;
}
__device__ __forceinline__ float nan_to_zero(float v) {
    return is_nan_bits(v) ? 0.0f : v;
}
__device__ __forceinline__ void split2(float2 v, unsigned& hi, unsigned& lo) {
    unsigned h;
    asm("cvt.rn.bf16x2.f32 %0, %1, %2;" : "=r"(h) : "f"(v.y), "f"(v.x));
    float h0 = __uint_as_float(h << 16);
    float h1 = __uint_as_float(h & 0xffff0000u);
    unsigned l;
    asm("cvt.rn.bf16x2.f32 %0, %1, %2;" : "=r"(l) : "f"(v.y - h1), "f"(v.x - h0));
    hi = h;
    lo = l;
}
__device__ __forceinline__ unsigned pack_f16x2(float lo, float hi) {
    unsigned u;
    asm("cvt.rn.f16x2.f32 %0, %1, %2;" : "=r"(u) : "f"(hi), "f"(lo));
    return u;
}
__device__ __forceinline__ float2 unpack_f16x2(unsigned u) {
    __half2 h = *reinterpret_cast<const __half2*>(&u);
    return __half22float2(h);
}
__device__ __forceinline__ void mma_bf16(float* c, unsigned a0, unsigned a1,
                                         unsigned a2, unsigned a3,
                                         unsigned b0, unsigned b1) {
    asm volatile(
        "mma.sync.aligned.m16n8k16.row.col.f32.bf16.bf16.f32 "
        "{%0,%1,%2,%3}, {%4,%5,%6,%7}, {%8,%9}, {%0,%1,%2,%3};"
        : "+f"(c[0]), "+f"(c[1]), "+f"(c[2]), "+f"(c[3])
        : "r"(a0), "r"(a1), "r"(a2), "r"(a3), "r"(b0), "r"(b1));
}

// -------- 1. init counters + pool + dtype detect --------
__global__ void init_kernel(const int* __restrict__ eraw) {
    int t = blockIdx.x * blockDim.x + threadIdx.x;
    if (t == 0) {
        int any = 0;
#pragma unroll
        for (int k = 0; k < 64; k++) any |= eraw[2 * k + 1];
        d_is64g = (any == 0) ? 1 : 0;
    }
    if (t < N_NODES) {
        d_deg[t] = 0.0f;
        d_cnt[t] = 0;
        d_cur[t] = 0;
    }
    if (t < NGRAPH * HDIM) d_pool[t] = 0.0f;
}

// -------- 2. side stream: edge convert + |w| + degree atomics + bounds --------
__global__ void cvt_edge_kernel(const int* __restrict__ eraw,
                                const int* __restrict__ braw,
                                const float* __restrict__ attr) {
    int t = blockIdx.x * blockDim.x + threadIdx.x;
    int is64 = d_is64g;
    if (t < N_EDGES) {
        int r, c;
        if (is64) {
            r = eraw[2 * t];
            c = eraw[2 * (N_EDGES + t)];
        } else {
            r = eraw[t];
            c = eraw[N_EDGES + t];
        }
        d_row[t] = r;
        d_col[t] = c;
        float w = fabsf(nan_to_zero(attr[t]));
        d_wabs[t] = w;
        atomicAdd(&d_deg[c], w);
        atomicAdd(&d_cnt[c], 1);
    }
    if (t < N_NODES) {
        int b    = is64 ? braw[2 * t] : braw[t];
        int prev = (t == 0) ? -1 : (is64 ? braw[2 * (t - 1)] : braw[t - 1]);
        if (prev != b) {
            for (int g = prev + 1; g <= b; g++) d_gstart[g] = t;
        }
        if (t == N_NODES - 1) {
            for (int g = b + 1; g <= NGRAPH; g++) d_gstart[g] = N_NODES;
        }
    }
}

// -------- 3. main stream: feature init (split bf16) + W prep --------
__global__ void feat_init_kernel(const float* __restrict__ x,
                                 const float* __restrict__ W0,
                                 const float* __restrict__ W1,
                                 const float* __restrict__ W2) {
    int t = blockIdx.x * blockDim.x + threadIdx.x;
    if (t < FEAT_N) {
        int i = t >> 6;
        int kq = t & 63;
        int f0 = kq * 2;
        float v0, v1;
        if (f0 < FIN) {
            v0 = nan_to_zero(x[i * FIN + f0]);
            v1 = nan_to_zero(x[i * FIN + f0 + 1]);
        } else {
            v0 = is_nan_bits(x[i * FIN + f0 - FIN]) ? 1.0f : 0.0f;
            v1 = is_nan_bits(x[i * FIN + f0 + 1 - FIN]) ? 1.0f : 0.0f;
        }
        unsigned hi, lo;
        split2(make_float2(v0, v1), hi, lo);
        d_hS[t] = make_uint2(hi, lo);
    } else if (t < FEAT_N + WPREP_N) {
        int u = t - FEAT_N;
        int layer = u >> 12;
        int rem = u & 4095;
        int ks = rem >> 9;
        int n = (rem >> 2) & 127;
        int q = rem & 3;
        const float* W = (layer == 0) ? W0 : (layer == 1) ? W1 : W2;
        int kb = ks * 16 + 2 * q;
        float2 vA = make_float2(W[kb * HDIM + n],       W[(kb + 1) * HDIM + n]);
        float2 vB = make_float2(W[(kb + 8) * HDIM + n], W[(kb + 9) * HDIM + n]);
        unsigned hA, lA, hB, lB;
        split2(vA, hA, lA);
        split2(vB, hB, lB);
        uint4 pk;
        pk.x = hA;
        pk.y = hB;
        pk.z = lA;
        pk.w = lB;
        d_Wt[layer][ks][n][q] = pk;
    }
}

// -------- 4. GEMM: 32x64 warp tile, pre-split A, fp16 epilogue --------
__global__ void __launch_bounds__(256, 2) gemm_mma_kernel(int layer) {
    const int tid = threadIdx.x;
    const int wid = tid >> 5;
    const int lane = tid & 31;
    const int wrow = wid >> 1;
    const int wcol = wid & 1;
    const int row_base = blockIdx.x * 128 + wrow * 32;
    const int col_base = wcol * 64;
    const int r = lane >> 2;            // 0..7
    const int lq = lane & 3;            // 0..3

    float acc[2][8][4];
#pragma unroll
    for (int mt = 0; mt < 2; mt++)
#pragma unroll
        for (int nt = 0; nt < 8; nt++)
#pragma unroll
            for (int j = 0; j < 4; j++) acc[mt][nt][j] = 0.0f;

#pragma unroll
    for (int ks = 0; ks < 8; ks++) {
        const int kq = ks * 8 + lq;
        unsigned ahi[2][4], alo[2][4];
#pragma unroll
        for (int mt = 0; mt < 2; mt++) {
            int r0 = row_base + mt * 16 + r;
            int r1 = r0 + 8;
            uint2 z = make_uint2(0u, 0u);
            uint2 p0 = (r0 < N_NODES) ? d_hS[r0 * 64 + kq]     : z;
            uint2 p1 = (r1 < N_NODES) ? d_hS[r1 * 64 + kq]     : z;
            uint2 p2 = (r0 < N_NODES) ? d_hS[r0 * 64 + kq + 4] : z;
            uint2 p3 = (r1 < N_NODES) ? d_hS[r1 * 64 + kq + 4] : z;
            ahi[mt][0] = p0.x; alo[mt][0] = p0.y;
            ahi[mt][1] = p1.x; alo[mt][1] = p1.y;
            ahi[mt][2] = p2.x; alo[mt][2] = p2.y;
            ahi[mt][3] = p3.x; alo[mt][3] = p3.y;
        }
        const uint4* wbase = &d_Wt[layer][ks][col_base][0];
#pragma unroll
        for (int nt = 0; nt < 8; nt++) {
            uint4 w = wbase[nt * 32 + lane];
#pragma unroll
            for (int mt = 0; mt < 2; mt++) {
                mma_bf16(acc[mt][nt], ahi[mt][0], ahi[mt][1], ahi[mt][2], ahi[mt][3], w.x, w.y);
                mma_bf16(acc[mt][nt], ahi[mt][0], ahi[mt][1], ahi[mt][2], ahi[mt][3], w.z, w.w);
                mma_bf16(acc[mt][nt], alo[mt][0], alo[mt][1], alo[mt][2], alo[mt][3], w.x, w.y);
            }
        }
    }
    // epilogue: pack to fp16x2
#pragma unroll
    for (int mt = 0; mt < 2; mt++) {
        int r0 = row_base + mt * 16 + r;
        int r1 = r0 + 8;
#pragma unroll
        for (int nt = 0; nt < 8; nt++) {
            int cc = col_base + nt * 8 + (lq * 2);
            if (r0 < N_NODES)
                d_hH[r0 * 64 + (cc >> 1)] = pack_f16x2(acc[mt][nt][0], acc[mt][nt][1]);
            if (r1 < N_NODES)
                d_hH[r1 * 64 + (cc >> 1)] = pack_f16x2(acc[mt][nt][2], acc[mt][nt][3]);
        }
    }
}

// -------- scan / scatter --------
__global__ void scan1_kernel() {
    __shared__ int sh[1024];
    int t = threadIdx.x;
    int b = blockIdx.x;
    int i = b * 1024 + t;
    int v = (i < N_NODES) ? d_cnt[i] : 0;
    sh[t] = v;
    __syncthreads();
#pragma unroll
    for (int ofs = 1; ofs < 1024; ofs <<= 1) {
        int u = (t >= ofs) ? sh[t - ofs] : 0;
        __syncthreads();
        sh[t] += u;
        __syncthreads();
    }
    if (i < N_NODES) d_off[i] = sh[t] - v;
    if (t == 1023) d_bsum[b] = sh[1023];
}
__global__ void scan2_kernel() {
    __shared__ int pre[SCAN_NB + 1];
    int t = threadIdx.x;
    int b = blockIdx.x;
    if (t == 0) {
        int run = 0;
#pragma unroll
        for (int j = 0; j < SCAN_NB; j++) { pre[j] = run; run += d_bsum[j]; }
        pre[SCAN_NB] = run;
    }
    __syncthreads();
    int i = b * 1024 + t;
    if (i < N_NODES) d_off[i] += pre[b];
    if (b == 0 && t == 0) d_off[N_NODES] = pre[SCAN_NB];
}
__global__ void scatter_kernel() {
    int e = blockIdx.x * blockDim.x + threadIdx.x;
    if (e >= N_EDGES) return;
    int r = d_row[e];
    int c = d_col[e];
    float w = d_wabs[e];
    int p = d_off[c] + atomicAdd(&d_cur[c], 1);
    float nrm = rsqrtf(d_deg[r] + 1.0f) * w * rsqrtf(d_deg[c] + 1.0f);
    int2 pk;
    pk.x = r;
    pk.y = __float_as_int(nrm);
    d_edge[p] = pk;
}

// -------- aggregation v3: 2 nodes/warp, 16 lanes/node, uint4 gathers --------
template <bool DO_BN>
__global__ void __launch_bounds__(512) agg_kernel(const float* __restrict__ bias,
                           const float* __restrict__ gamma,
                           const float* __restrict__ beta,
                           const float* __restrict__ mean,
                           const float* __restrict__ var) {
    int warp = (blockIdx.x * blockDim.x + threadIdx.x) >> 5;
    int lane = threadIdx.x & 31;
    int half = lane >> 4;            // 0 or 1
    int lane16 = lane & 15;          // 0..15
    int i = warp * 2 + half;
    if (i >= N_NODES) return;
    const int fs = lane16 * 8;       // feature base (8 features per lane)
    const uint4* __restrict__ hrows = reinterpret_cast<const uint4*>(d_hH);  // 16 uint4 per row
    int s = d_off[i];
    int e = d_off[i + 1];

    float acc[8];
#pragma unroll
    for (int j = 0; j < 8; j++) acc[j] = 0.0f;

    int p = s;
    for (; p + 3 < e; p += 4) {
        int2 em[4];
        uint4 q[4];
#pragma unroll
        for (int j = 0; j < 4; j++) em[j] = d_edge[p + j];
#pragma unroll
        for (int j = 0; j < 4; j++) q[j] = hrows[em[j].x * 16 + lane16];
#pragma unroll
        for (int j = 0; j < 4; j++) {
            float n = __int_as_float(em[j].y);
            float2 a = unpack_f16x2(q[j].x);
            float2 b = unpack_f16x2(q[j].y);
            float2 c = unpack_f16x2(q[j].z);
            float2 d = unpack_f16x2(q[j].w);
            acc[0] += n * a.x; acc[1] += n * a.y;
            acc[2] += n * b.x; acc[3] += n * b.y;
            acc[4] += n * c.x; acc[5] += n * c.y;
            acc[6] += n * d.x; acc[7] += n * d.y;
        }
    }
    for (; p < e; p++) {
        int2 em = d_edge[p];
        float n = __int_as_float(em.y);
        uint4 q = hrows[em.x * 16 + lane16];
        float2 a = unpack_f16x2(q.x);
        float2 b = unpack_f16x2(q.y);
        float2 c = unpack_f16x2(q.z);
        float2 d = unpack_f16x2(q.w);
        acc[0] += n * a.x; acc[1] += n * a.y;
        acc[2] += n * b.x; acc[3] += n * b.y;
        acc[4] += n * c.x; acc[5] += n * c.y;
        acc[6] += n * d.x; acc[7] += n * d.y;
    }
    // self loop
    {
        float sl = 1.0f / (d_deg[i] + 1.0f);
        uint4 q = hrows[i * 16 + lane16];
        float2 a = unpack_f16x2(q.x);
        float2 b = unpack_f16x2(q.y);
        float2 c = unpack_f16x2(q.z);
        float2 d = unpack_f16x2(q.w);
        acc[0] += sl * a.x; acc[1] += sl * a.y;
        acc[2] += sl * b.x; acc[3] += sl * b.y;
        acc[4] += sl * c.x; acc[5] += sl * c.y;
        acc[6] += sl * d.x; acc[7] += sl * d.y;
    }
#pragma unroll
    for (int j = 0; j < 8; j++) acc[j] += bias[fs + j];

    if (DO_BN) {
#pragma unroll
        for (int j = 0; j < 8; j++) {
            float sc = gamma[fs + j] * rsqrtf(var[fs + j] + 1e-5f);
            acc[j] = fmaxf(0.0f, (acc[j] - mean[fs + j]) * sc + beta[fs + j]);
        }
        // split 4 k-pairs to bf16 hi/lo, store as 2 uint4
        unsigned h[4], l[4];
        split2(make_float2(acc[0], acc[1]), h[0], l[0]);
        split2(make_float2(acc[2], acc[3]), h[1], l[1]);
        split2(make_float2(acc[4], acc[5]), h[2], l[2]);
        split2(make_float2(acc[6], acc[7]), h[3], l[3]);
        uint4* dst = reinterpret_cast<uint4*>(&d_hS[i * 64 + lane16 * 4]);
        dst[0] = make_uint4(h[0], l[0], h[1], l[1]);
        dst[1] = make_uint4(h[2], l[2], h[3], l[3]);
    } else {
        float4* dst = reinterpret_cast<float4*>(&d_hA[i * HDIM + fs]);
        dst[0] = make_float4(acc[0], acc[1], acc[2], acc[3]);
        dst[1] = make_float4(acc[4], acc[5], acc[6], acc[7]);
    }
}

// -------- pool + MLP --------
__global__ void pool_kernel() {
    int g = blockIdx.x;
    int part = blockIdx.y;
    int f = threadIdx.x;
    int s = d_gstart[g];
    int e = d_gstart[g + 1];
    int len = e - s;
    int chunk = (len + POOL_SPLIT - 1) / POOL_SPLIT;
    int ps = s + part * chunk;
    int pe = min(ps + chunk, e);
    float a = 0.f;
    for (int n = ps; n < pe; n++) a += d_hA[n * HDIM + f];
    float cnt = (float)len;
    if (ps < pe) atomicAdd(&d_pool[g * HDIM + f], a / fmaxf(cnt, 1.0f));
}
__global__ void mlp_kernel(const float* __restrict__ mW1,
                           const float* __restrict__ mb1,
                           const float* __restrict__ mW2,
                           const float* __restrict__ mb2,
                           float* __restrict__ out) {
    __shared__ __align__(16) float gi[HDIM];
    __shared__ __align__(16) float hid[HDIM];
    int g = blockIdx.x;
    int t = threadIdx.x;
    gi[t] = d_pool[g * HDIM + t];
    __syncthreads();
    float acc = mb1[t];
#pragma unroll 4
    for (int k = 0; k < HDIM; k++) acc += gi[k] * mW1[k * HDIM + t];
    hid[t] = 0.5f * acc * (1.0f + erff(acc * 0.70710678118654752f));
    __syncthreads();
    if (t < NOUT) {
        float o = mb2[t];
#pragma unroll 4
        for (int k = 0; k < HDIM; k++) o += hid[k] * mW2[k * NOUT + t];
        out[g * NOUT + t] = o;
    }
}

// -------- launch --------
extern "C" void kernel_launch(void* const* d_in, const int* in_sizes, int n_in,
                              void* d_out, int out_size) {
    const float* x     = (const float*)d_in[0];
    const int*   eraw  = (const int*)d_in[1];
    const float* attr  = (const float*)d_in[2];
    const int*   braw  = (const int*)d_in[3];
    const float* W0 = (const float*)d_in[4];
    const float* b0 = (const float*)d_in[5];
    const float* W1 = (const float*)d_in[6];
    const float* b1 = (const float*)d_in[7];
    const float* W2 = (const float*)d_in[8];
    const float* b2 = (const float*)d_in[9];
    const float* bn_gamma = (const float*)d_in[10];
    const float* bn_beta  = (const float*)d_in[11];
    const float* bn_mean  = (const float*)d_in[12];
    const float* bn_var   = (const float*)d_in[13];
    const float* mW1 = (const float*)d_in[14];
    const float* mb1 = (const float*)d_in[15];
    const float* mW2 = (const float*)d_in[16];
    const float* mb2 = (const float*)d_in[17];
    float* out = (float*)d_out;

    static cudaStream_t s2 = nullptr;
    static cudaEvent_t evA = nullptr, evB = nullptr;
    if (s2 == nullptr) {
        cudaStreamCreateWithFlags(&s2, cudaStreamNonBlocking);
        cudaEventCreateWithFlags(&evA, cudaEventDisableTiming);
        cudaEventCreateWithFlags(&evB, cudaEventDisableTiming);
    }

    const int TB = 256;
    // 2 nodes per warp, 16 warps per 512-thread block -> 32 nodes/block
    const int agg_blocks = (N_NODES + 31) / 32;

    // main stream: init -> feat_init(+wprep) -> gemm0
    init_kernel<<<(N_NODES + TB - 1) / TB, TB>>>(eraw);
    cudaEventRecord(evA, 0);
    feat_init_kernel<<<(FEAT_N + WPREP_N + TB - 1) / TB, TB>>>(x, W0, W1, W2);
    gemm_mma_kernel<<<GEMM_BLOCKS, 256>>>(0);

    // side stream (forked after init): CSR build
    cudaStreamWaitEvent(s2, evA, 0);
    cvt_edge_kernel<<<(N_EDGES + TB - 1) / TB, TB, 0, s2>>>(eraw, braw, attr);
    scan1_kernel<<<SCAN_NB, 1024, 0, s2>>>();
    scan2_kernel<<<SCAN_NB, 1024, 0, s2>>>();
    scatter_kernel<<<(N_EDGES + TB - 1) / TB, TB, 0, s2>>>();
    cudaEventRecord(evB, s2);

    // join
    cudaStreamWaitEvent(0, evB, 0);
    agg_kernel<true><<<agg_blocks, 512>>>(b0, bn_gamma, bn_beta, bn_mean, bn_var);
    gemm_mma_kernel<<<GEMM_BLOCKS, 256>>>(1);
    agg_kernel<true><<<agg_blocks, 512>>>(b1, bn_gamma, bn_beta, bn_mean, bn_var);
    gemm_mma_kernel<<<GEMM_BLOCKS, 256>>>(2);
    agg_kernel<false><<<agg_blocks, 512>>>(b2, bn_gamma, bn_beta, bn_mean, bn_var);

    dim3 pool_grid(NGRAPH, POOL_SPLIT);
    pool_kernel<<<pool_grid, HDIM>>>();
    mlp_kernel<<<NGRAPH, HDIM>>>(mW1, mb1, mW2, mb2, out);
}